// round 1
// baseline (speedup 1.0000x reference)
#include <cuda_runtime.h>
#include <cuda_bf16.h>

// Problem constants (fixed shapes per reference setup_inputs)
#define BB 8
#define CC 3
#define HH 224
#define WW 224
#define NPIX (HH * WW)          // 50176
#define NSEG 196
#define EE 768
#define NROWS (BB * NSEG)       // 1568
#define ACC_STRIDE 8            // [sum_r, sum_g, sum_b, sum_x, sum_y, cnt, pad, pad]

// Scratch accumulator: 1568 * 8 floats = 50176 B (device global, no allocation)
__device__ float g_acc[NROWS * ACC_STRIDE];

// ---------------------------------------------------------------------------
// Vector global reductions (sm_90+): 2 RED ops per pixel instead of 6
// ---------------------------------------------------------------------------
__device__ __forceinline__ void red_add_v4(float* addr, float a, float b,
                                           float c, float d) {
    asm volatile("red.global.add.v4.f32 [%0], {%1, %2, %3, %4};"
                 :: "l"(addr), "f"(a), "f"(b), "f"(c), "f"(d) : "memory");
}
__device__ __forceinline__ void red_add_v2(float* addr, float a, float b) {
    asm volatile("red.global.add.v2.f32 [%0], {%1, %2};"
                 :: "l"(addr), "f"(a), "f"(b) : "memory");
}

// ---------------------------------------------------------------------------
// Kernel 0: zero the accumulator
// ---------------------------------------------------------------------------
__global__ void zero_acc_kernel() {
    int i = blockIdx.x * blockDim.x + threadIdx.x;   // float4 index
    const int n4 = (NROWS * ACC_STRIDE) / 4;         // 3136
    if (i < n4) {
        reinterpret_cast<float4*>(g_acc)[i] = make_float4(0.f, 0.f, 0.f, 0.f);
    }
}

// ---------------------------------------------------------------------------
// Kernel 1: per-(batch,segment) feature sums.
// Each thread handles 4 consecutive pixels in one row (224 % 4 == 0, so a
// group never crosses a row boundary). float4/int4 coalesced loads.
// ---------------------------------------------------------------------------
__global__ void scatter_kernel(const float* __restrict__ img,
                               const int* __restrict__ seg) {
    int t = blockIdx.x * blockDim.x + threadIdx.x;
    const int ngroups = (BB * NPIX) / 4;             // 100352
    if (t >= ngroups) return;

    int b  = t / (NPIX / 4);
    int n4 = t - b * (NPIX / 4);
    int n  = n4 * 4;                                 // pixel linear index in image
    int h  = n / WW;
    int w  = n - h * WW;

    const float4 r4 = *reinterpret_cast<const float4*>(img + ((long)(b * CC + 0) * NPIX + n));
    const float4 g4 = *reinterpret_cast<const float4*>(img + ((long)(b * CC + 1) * NPIX + n));
    const float4 b4 = *reinterpret_cast<const float4*>(img + ((long)(b * CC + 2) * NPIX + n));
    const int4  s4 = *reinterpret_cast<const int4*>(seg + (long)b * NPIX + n);

    const float inv = 1.0f / 223.0f;
    float y = (float)h * inv;
    float x0 = (float)w * inv;

    float rr[4] = {r4.x, r4.y, r4.z, r4.w};
    float gg[4] = {g4.x, g4.y, g4.z, g4.w};
    float bb[4] = {b4.x, b4.y, b4.z, b4.w};
    int   ss[4] = {s4.x, s4.y, s4.z, s4.w};

#pragma unroll
    for (int i = 0; i < 4; i++) {
        float x = (float)(w + i) * inv;
        (void)x0;
        float* base = g_acc + (long)(b * NSEG + ss[i]) * ACC_STRIDE;
        red_add_v4(base, rr[i], gg[i], bb[i], x);
        red_add_v2(base + 4, y, 1.0f);
    }
}

// ---------------------------------------------------------------------------
// Kernel 2: project segment means: out[s, e] = mean_feat[s] . W[:, e] + b[e]
// One block per (batch,segment) row; 256 threads x 3 columns each.
// W (15 KB) lives in L1/L2 after first block touches it.
// ---------------------------------------------------------------------------
__global__ void project_kernel(const float* __restrict__ Wm,
                               const float* __restrict__ bias,
                               float* __restrict__ out) {
    int s = blockIdx.x;                              // 0..1567
    const float* a = g_acc + (long)s * ACC_STRIDE;
    float cnt = a[5];
    bool  empty = !(cnt > 0.0f);
    float invc = empty ? 0.0f : (1.0f / cnt);
    float m0 = a[0] * invc;
    float m1 = a[1] * invc;
    float m2 = a[2] * invc;
    float m3 = a[3] * invc;
    float m4 = a[4] * invc;

    float* orow = out + (long)s * EE;
#pragma unroll
    for (int k = 0; k < 3; k++) {
        int e = threadIdx.x + k * 256;
        float v = m0 * Wm[e]
                + m1 * Wm[EE + e]
                + m2 * Wm[2 * EE + e]
                + m3 * Wm[3 * EE + e]
                + m4 * Wm[4 * EE + e]
                + bias[e];
        orow[e] = empty ? 0.0f : v;
    }
}

// ---------------------------------------------------------------------------
extern "C" void kernel_launch(void* const* d_in, const int* in_sizes, int n_in,
                              void* d_out, int out_size) {
    const float* img  = (const float*)d_in[0];   // [8,3,224,224]
    const int*   seg  = (const int*)d_in[1];     // [8,224,224]
    const float* Wm   = (const float*)d_in[2];   // [5,768]
    const float* bias = (const float*)d_in[3];   // [768]
    float* out = (float*)d_out;                  // [8,196,768]

    (void)in_sizes; (void)n_in; (void)out_size;

    // zero accumulator: 3136 float4s
    zero_acc_kernel<<<(3136 + 255) / 256, 256>>>();

    // scatter: 100352 threads
    scatter_kernel<<<(100352 + 255) / 256, 256>>>(img, seg);

    // projection: 1568 rows
    project_kernel<<<NROWS, 256>>>(Wm, bias, out);
}